// round 6
// baseline (speedup 1.0000x reference)
#include <cuda_runtime.h>
#include <cuda_bf16.h>
#include <cstdint>

// ---------------- problem constants ----------------
#define Bz  4
#define NSz 10000
#define NTz 10000
#define Ez  160000
#define Kz  16
#define Dd  128
#define TM  128          // rows per CTA tile
#define NTHR 256
#define NPB 313          // ceil(40000/128)
#define DPITCH 132       // D staging pitch (floats); 528B/row = 33*16 -> float4-aligned

// ---------------- scratch (__device__ globals; no allocation) ----------------
__device__ float g_sproj[(size_t)Bz * NSz * Dd];
__device__ float g_tproj[(size_t)Bz * NTz * Dd];
__device__ float g_dbond[(size_t)Bz * Ez  * Dd];
// Pre-swizzled bf16 hi/lo smem images of the 5 weight matrices, B-operand
// layout B[n][k] = W[k][n]. [w][0]=hi, [w][1]=lo. 2048 uint4 = 32KB each.
__device__ uint4 g_Wimg[5][2][2048];

// ---------------- smem layout (byte offsets) ----------------
#define SM_AHI 0
#define SM_ALO 32768
#define SM_BHI 65536
#define SM_BLO 98304
#define SMEM_SZ 131072
#define SM_D   0         // fp32 D staging overlays A/B after MMA (128*132*4 = 67584)

// ---------------- low-level helpers ----------------
static __device__ __forceinline__ uint32_t s2u(const void* p) {
    uint32_t a;
    asm("{ .reg .u64 t; cvta.to.shared.u64 t, %1; cvt.u32.u64 %0, t; }" : "=r"(a) : "l"(p));
    return a;
}
static __device__ __forceinline__ void ldsm_x4(uint32_t& r0, uint32_t& r1, uint32_t& r2,
                                               uint32_t& r3, uint32_t addr) {
    asm volatile("ldmatrix.sync.aligned.m8n8.x4.shared.b16 {%0,%1,%2,%3}, [%4];"
                 : "=r"(r0), "=r"(r1), "=r"(r2), "=r"(r3) : "r"(addr));
}
static __device__ __forceinline__ void mma16816(float* c,
        uint32_t a0, uint32_t a1, uint32_t a2, uint32_t a3, uint32_t b0, uint32_t b1) {
    asm volatile(
        "mma.sync.aligned.m16n8k16.row.col.f32.bf16.bf16.f32 "
        "{%0,%1,%2,%3}, {%4,%5,%6,%7}, {%8,%9}, {%0,%1,%2,%3};"
        : "+f"(c[0]), "+f"(c[1]), "+f"(c[2]), "+f"(c[3])
        : "r"(a0), "r"(a1), "r"(a2), "r"(a3), "r"(b0), "r"(b1));
}
static __device__ __forceinline__ float silu_f(float v) {
    return v * (1.0f / (1.0f + __expf(-v)));
}

// fp32[8] -> bf16 hi/lo packed uint4s (hi = rn(x), lo = rn(x - hi))
static __device__ __forceinline__ void cvt8(const float* f, uint4& h4, uint4& l4) {
    uint32_t h[4], l[4];
#pragma unroll
    for (int i = 0; i < 4; ++i) {
        float a = f[2*i], b = f[2*i+1];
        __nv_bfloat162 hh = __floats2bfloat162_rn(a, b);
        float la = a - __bfloat162float(hh.x);
        float lb = b - __bfloat162float(hh.y);
        __nv_bfloat162 ll = __floats2bfloat162_rn(la, lb);
        h[i] = *reinterpret_cast<uint32_t*>(&hh);
        l[i] = *reinterpret_cast<uint32_t*>(&ll);
    }
    h4 = make_uint4(h[0], h[1], h[2], h[3]);
    l4 = make_uint4(l[0], l[1], l[2], l[3]);
}

// Tile smem addressing: row-major [row][128 bf16], 256B/row, 16B-unit XOR swizzle.
// element (r, c): r*256 + ((c>>3) ^ (r&7))*16 + (c&7)*2
static __device__ __forceinline__ uint32_t tile_unit_off(int row, int u) {
    return (uint32_t)(row * 256 + ((u ^ (row & 7)) << 4));
}

// Fill A tile (128 rows of X starting at row0) as bf16 hi/lo. All 256 threads.
static __device__ __forceinline__ void fill_A(char* sm, const float* __restrict__ X,
                                              size_t row0, size_t total, int tid) {
#pragma unroll
    for (int it = 0; it < 8; ++it) {
        int idx = tid + it * NTHR;        // 0..2047 = 128 rows x 16 units
        int row = idx >> 4;
        int u   = idx & 15;
        size_t g = row0 + row;
        if (g < total) {
            const float4* p = (const float4*)(X + g * Dd + u * 8);
            float4 v0 = p[0], v1 = p[1];
            float f[8] = {v0.x, v0.y, v0.z, v0.w, v1.x, v1.y, v1.z, v1.w};
            uint4 h, l; cvt8(f, h, l);
            uint32_t off = tile_unit_off(row, u);
            *(uint4*)(sm + SM_AHI + off) = h;
            *(uint4*)(sm + SM_ALO + off) = l;
        }
    }
}

// Copy pre-swizzled weight image into B buffers. All 256 threads.
static __device__ __forceinline__ void copy_B(char* sm, int wi, int tid) {
    const uint4* hi = g_Wimg[wi][0];
    const uint4* lo = g_Wimg[wi][1];
    uint4* dh = (uint4*)(sm + SM_BHI);
    uint4* dl = (uint4*)(sm + SM_BLO);
#pragma unroll
    for (int it = 0; it < 8; ++it) {
        int i = tid + it * NTHR;
        dh[i] = hi[i];
        dl[i] = lo[i];
    }
}

// One GEMM term: acc += A_tile(a_off) @ B_tile(b_off)^T over k=128.
// Warp tile: rows mq*32..+31, cols nh*64..+63.
static __device__ __forceinline__ void warp_gemm_term(
        uint32_t sb, uint32_t a_off, uint32_t b_off,
        int mq, int nh, int lane, float acc[2][8][4]) {
    int rA = (lane & 7) + ((lane >> 3) & 1) * 8;   // row-in-m16
    int uA = lane >> 4;                            // k-unit select
    int rB = (lane & 7) + ((lane >> 4) << 3);      // row-in-n16 pair
    int uB = (lane >> 3) & 1;
    int x  = lane & 7;                             // swizzle xor (row&7)
    uint32_t baseA0 = sb + a_off + (uint32_t)((mq * 32 + rA) * 256);
    uint32_t baseA1 = baseA0 + 16 * 256;
    uint32_t baseB[4];
#pragma unroll
    for (int nb = 0; nb < 4; ++nb)
        baseB[nb] = sb + b_off + (uint32_t)((nh * 64 + nb * 16 + rB) * 256);
#pragma unroll
    for (int ks = 0; ks < 8; ++ks) {
        uint32_t oA = (uint32_t)(((((ks << 1) + uA)) ^ x) << 4);
        uint32_t oB = (uint32_t)(((((ks << 1) + uB)) ^ x) << 4);
        uint32_t a0, a1, a2, a3, a4, a5, a6, a7;
        ldsm_x4(a0, a1, a2, a3, baseA0 + oA);
        ldsm_x4(a4, a5, a6, a7, baseA1 + oA);
#pragma unroll
        for (int nb = 0; nb < 4; ++nb) {
            uint32_t b0, b1, b2, b3;
            ldsm_x4(b0, b1, b2, b3, baseB[nb] + oB);
            mma16816(acc[0][2*nb],     a0, a1, a2, a3, b0, b1);
            mma16816(acc[0][2*nb + 1], a0, a1, a2, a3, b2, b3);
            mma16816(acc[1][2*nb],     a4, a5, a6, a7, b0, b1);
            mma16816(acc[1][2*nb + 1], a4, a5, a6, a7, b2, b3);
        }
    }
}

static __device__ __forceinline__ void gemm3(uint32_t sb, int mq, int nh, int lane,
                                             float acc[2][8][4]) {
    warp_gemm_term(sb, SM_AHI, SM_BHI, mq, nh, lane, acc);   // hi*hi
    warp_gemm_term(sb, SM_AHI, SM_BLO, mq, nh, lane, acc);   // hi*lo
    warp_gemm_term(sb, SM_ALO, SM_BHI, mq, nh, lane, acc);   // lo*hi
}

// Stage accumulators into smem D (fp32, pitch DPITCH). Caller syncs before/after.
static __device__ __forceinline__ void store_D(char* sm, int mq, int nh, int lane,
                                               float acc[2][8][4]) {
    float* D = (float*)(sm + SM_D);
#pragma unroll
    for (int i = 0; i < 2; ++i) {
        int r0 = mq * 32 + i * 16 + (lane >> 2);
#pragma unroll
        for (int j = 0; j < 8; ++j) {
            int c = nh * 64 + j * 8 + (lane & 3) * 2;
            *(float2*)(D + r0 * DPITCH + c)       = make_float2(acc[i][j][0], acc[i][j][1]);
            *(float2*)(D + (r0 + 8) * DPITCH + c) = make_float2(acc[i][j][2], acc[i][j][3]);
        }
    }
}

// ---------------- kernel 0: split all 5 weights into swizzled bf16 images ----------------
extern "C" __global__ void __launch_bounds__(NTHR, 4)
setup_kernel(const float* __restrict__ W0, const float* __restrict__ W1,
             const float* __restrict__ W2, const float* __restrict__ W3,
             const float* __restrict__ W4) {
    const float* Ws[5] = {W0, W1, W2, W3, W4};
    int w = blockIdx.x >> 2, part = blockIdx.x & 3;
    const float* W = Ws[w];
    int tid = threadIdx.x;
#pragma unroll
    for (int it = 0; it < 2; ++it) {
        int idx = part * 512 + tid + it * NTHR;   // 0..2047 = 128 n-rows x 16 units
        int n = idx >> 4;
        int u = idx & 15;
        float f[8];
#pragma unroll
        for (int i = 0; i < 8; ++i) f[i] = W[(u * 8 + i) * Dd + n];   // B[n][k]=W[k][n]
        uint4 h, l; cvt8(f, h, l);
        uint32_t off16 = tile_unit_off(n, u) >> 4;
        g_Wimg[w][0][off16] = h;
        g_Wimg[w][1][off16] = l;
    }
}

// ---------------- kernel 1: node projections ----------------
extern "C" __global__ void __launch_bounds__(NTHR, 1)
proj_kernel(const float* __restrict__ src, const float* __restrict__ tgt) {
    extern __shared__ char sm[];
    uint32_t sb = s2u(sm);
    int tid = threadIdx.x;
    int lane = tid & 31, w = tid >> 5, mq = w & 3, nh = w >> 2;
    const size_t total = (size_t)Bz * NSz;   // 40000

    int blk = blockIdx.x;
    const float* X; int wi; float* Y;
    if (blk < NPB) { X = src; wi = 0; Y = g_sproj; }
    else           { blk -= NPB; X = tgt; wi = 1; Y = g_tproj; }
    size_t row0 = (size_t)blk * TM;

    fill_A(sm, X, row0, total, tid);
    copy_B(sm, wi, tid);
    __syncthreads();

    float acc[2][8][4] = {};
    gemm3(sb, mq, nh, lane, acc);
    __syncthreads();
    store_D(sm, mq, nh, lane, acc);
    __syncthreads();

    const float* D = (const float*)(sm + SM_D);
#pragma unroll
    for (int it = 0; it < 16; ++it) {
        int unit = tid + it * NTHR;       // 128 rows x 32 float4
        int row = unit >> 5;
        int c4  = (unit & 31) * 4;
        size_t g = row0 + row;
        if (g < total)
            *(float4*)(Y + g * Dd + c4) = *(const float4*)(D + row * DPITCH + c4);
    }
}

// ---------------- kernel 2: bond update ----------------
extern "C" __global__ void __launch_bounds__(NTHR, 1)
bond_kernel(const float* __restrict__ bond,
            const int* __restrict__ src_order, const int* __restrict__ tgt_order,
            const float* __restrict__ lg, const float* __restrict__ lb,
            float* __restrict__ out0) {
    extern __shared__ char sm[];
    uint32_t sb = s2u(sm);
    int tid = threadIdx.x;
    int lane = tid & 31, w = tid >> 5, mq = w & 3, nh = w >> 2;
    size_t row0 = (size_t)blockIdx.x * TM;

    fill_A(sm, bond, row0, (size_t)Bz * Ez, tid);
    copy_B(sm, 2, tid);                     // W_e2e
    __syncthreads();

    float acc[2][8][4] = {};
    gemm3(sb, mq, nh, lane, acc);
    __syncthreads();
    store_D(sm, mq, nh, lane, acc);
    __syncthreads();

    // Epilogue: 2 threads per row, 64 cols each.
    const float* D = (const float*)(sm + SM_D);
    int r  = tid >> 1;
    int hf = (tid & 1) * 64;
    size_t grow = row0 + r;
    int b = (int)(grow / Ez);
    int e = (int)(grow - (size_t)b * Ez);
    int so = src_order[e];
    int to = tgt_order[e];
    const float4* sp = (const float4*)(g_sproj + ((size_t)b * NSz + so) * Dd + hf);
    const float4* tp = (const float4*)(g_tproj + ((size_t)b * NTz + to) * Dd + hf);
    const float*  dr = D + r * DPITCH + hf;

    float v[64];
    float s = 0.f, s2 = 0.f;
#pragma unroll
    for (int j = 0; j < 16; ++j) {
        float4 a = sp[j], c = tp[j];
        float v0 = silu_f(dr[4*j]     + a.x + c.x);
        float v1 = silu_f(dr[4*j + 1] + a.y + c.y);
        float v2 = silu_f(dr[4*j + 2] + a.z + c.z);
        float v3 = silu_f(dr[4*j + 3] + a.w + c.w);
        v[4*j] = v0; v[4*j+1] = v1; v[4*j+2] = v2; v[4*j+3] = v3;
        s  += v0 + v1 + v2 + v3;
        s2 += v0*v0 + v1*v1 + v2*v2 + v3*v3;
    }
    s  += __shfl_xor_sync(0xffffffffu, s, 1);
    s2 += __shfl_xor_sync(0xffffffffu, s2, 1);
    float m   = s * (1.0f / Dd);
    float var = s2 * (1.0f / Dd) - m * m;
    float rs  = rsqrtf(var + 1e-5f);

    const float4* gg = (const float4*)(lg + hf);
    const float4* bb = (const float4*)(lb + hf);
    const float4* bo = (const float4*)(bond + grow * Dd + hf);
    float4* dbw = (float4*)(g_dbond + grow * Dd + hf);
    float4* ow  = (float4*)(out0    + grow * Dd + hf);
#pragma unroll
    for (int j = 0; j < 16; ++j) {
        float4 g4 = gg[j], b4 = bb[j], bd = bo[j];
        float y0 = (v[4*j]   - m) * rs * g4.x + b4.x;
        float y1 = (v[4*j+1] - m) * rs * g4.y + b4.y;
        float y2 = (v[4*j+2] - m) * rs * g4.z + b4.z;
        float y3 = (v[4*j+3] - m) * rs * g4.w + b4.w;
        dbw[j] = make_float4(y0, y1, y2, y3);
        ow[j]  = make_float4(bd.x + y0, bd.y + y1, bd.z + y2, bd.w + y3);
    }
}

// ---------------- kernel 3: target update ----------------
extern "C" __global__ void __launch_bounds__(NTHR, 1)
tgt_kernel(const float* __restrict__ tgt,
           const float* __restrict__ coef, const int* __restrict__ eorder,
           const float* __restrict__ lg, const float* __restrict__ lb,
           float* __restrict__ out2) {
    extern __shared__ char sm[];
    uint32_t sb = s2u(sm);
    int tid = threadIdx.x;
    int lane = tid & 31, w = tid >> 5, mq = w & 3, nh = w >> 2;
    const size_t total = (size_t)Bz * NTz;   // 40000
    size_t row0 = (size_t)blockIdx.x * TM;

    // Phase A operand: bond_reduce rows (weighted mean of Kz gathered d_bond rows)
    {
        int r  = tid >> 1;
        int hf = (tid & 1) * 64;
        size_t grow = row0 + r;
        if (grow < total) {
            int b  = (int)(grow / NTz);
            int tt = (int)(grow - (size_t)b * NTz);
            const int*   eo = eorder + tt * Kz;
            const float* cf = coef   + tt * Kz;
            float4 a4[16];
#pragma unroll
            for (int j = 0; j < 16; ++j) a4[j] = make_float4(0.f, 0.f, 0.f, 0.f);
            for (int k = 0; k < Kz; ++k) {
                float c = cf[k];
                const float4* p = (const float4*)(g_dbond + ((size_t)b * Ez + eo[k]) * Dd + hf);
#pragma unroll
                for (int j = 0; j < 16; ++j) {
                    float4 vv = p[j];
                    a4[j].x = fmaf(c, vv.x, a4[j].x);
                    a4[j].y = fmaf(c, vv.y, a4[j].y);
                    a4[j].z = fmaf(c, vv.z, a4[j].z);
                    a4[j].w = fmaf(c, vv.w, a4[j].w);
                }
            }
#pragma unroll
            for (int jj = 0; jj < 8; ++jj) {
                float f[8] = {a4[2*jj].x   * (1.0f/Kz), a4[2*jj].y   * (1.0f/Kz),
                              a4[2*jj].z   * (1.0f/Kz), a4[2*jj].w   * (1.0f/Kz),
                              a4[2*jj+1].x * (1.0f/Kz), a4[2*jj+1].y * (1.0f/Kz),
                              a4[2*jj+1].z * (1.0f/Kz), a4[2*jj+1].w * (1.0f/Kz)};
                uint4 h, l; cvt8(f, h, l);
                uint32_t off = tile_unit_off(r, (hf >> 3) + jj);
                *(uint4*)(sm + SM_AHI + off) = h;
                *(uint4*)(sm + SM_ALO + off) = l;
            }
        }
    }
    copy_B(sm, 3, tid);                     // W_e2t
    __syncthreads();

    float acc[2][8][4] = {};
    gemm3(sb, mq, nh, lane, acc);           // bond_reduce @ W_e2t
    __syncthreads();

    fill_A(sm, tgt, row0, total, tid);      // refill A with tgt rows
    copy_B(sm, 4, tid);                     // W_t2t
    __syncthreads();
    gemm3(sb, mq, nh, lane, acc);           // += tgt @ W_t2t
    __syncthreads();
    store_D(sm, mq, nh, lane, acc);
    __syncthreads();

    const float* D = (const float*)(sm + SM_D);
    int r  = tid >> 1;
    int hf = (tid & 1) * 64;
    size_t grow = row0 + r;
    const float* dr = D + r * DPITCH + hf;

    float v[64];
    float s = 0.f, s2 = 0.f;
#pragma unroll
    for (int j = 0; j < 16; ++j) {
        float v0 = silu_f(dr[4*j]);
        float v1 = silu_f(dr[4*j + 1]);
        float v2 = silu_f(dr[4*j + 2]);
        float v3 = silu_f(dr[4*j + 3]);
        v[4*j] = v0; v[4*j+1] = v1; v[4*j+2] = v2; v[4*j+3] = v3;
        s  += v0 + v1 + v2 + v3;
        s2 += v0*v0 + v1*v1 + v2*v2 + v3*v3;
    }
    s  += __shfl_xor_sync(0xffffffffu, s, 1);
    s2 += __shfl_xor_sync(0xffffffffu, s2, 1);
    float m   = s * (1.0f / Dd);
    float var = s2 * (1.0f / Dd) - m * m;
    float rs  = rsqrtf(var + 1e-5f);

    if (grow < total) {
        const float4* gg = (const float4*)(lg + hf);
        const float4* bb = (const float4*)(lb + hf);
        const float4* tv = (const float4*)(tgt + grow * Dd + hf);
        float4* ow = (float4*)(out2 + grow * Dd + hf);
#pragma unroll
        for (int j = 0; j < 16; ++j) {
            float4 g4 = gg[j], b4 = bb[j], t4 = tv[j];
            ow[j] = make_float4(t4.x + (v[4*j]   - m) * rs * g4.x + b4.x,
                                t4.y + (v[4*j+1] - m) * rs * g4.y + b4.y,
                                t4.z + (v[4*j+2] - m) * rs * g4.z + b4.z,
                                t4.w + (v[4*j+3] - m) * rs * g4.w + b4.w);
        }
    }
}

// ---------------- launcher ----------------
extern "C" void kernel_launch(void* const* d_in, const int* in_sizes, int n_in,
                              void* d_out, int out_size) {
    const float* bond  = (const float*)d_in[0];
    const float* src   = (const float*)d_in[1];
    const float* tgt   = (const float*)d_in[2];
    const float* W_s2e = (const float*)d_in[3];
    const float* W_t2e = (const float*)d_in[4];
    const float* W_e2e = (const float*)d_in[5];
    const float* ln1g  = (const float*)d_in[6];
    const float* ln1b  = (const float*)d_in[7];
    const float* W_e2t = (const float*)d_in[8];
    const float* W_t2t = (const float*)d_in[9];
    const float* ln2g  = (const float*)d_in[10];
    const float* ln2b  = (const float*)d_in[11];
    const float* coef  = (const float*)d_in[12];
    const int*   so    = (const int*)d_in[13];
    const int*   to    = (const int*)d_in[14];
    const int*   eo    = (const int*)d_in[15];

    float* out0 = (float*)d_out;                         // [B,E,D]
    float* out1 = out0 + (size_t)Bz * Ez  * Dd;          // [B,NS,D] passthrough
    float* out2 = out1 + (size_t)Bz * NSz * Dd;          // [B,NT,D]

    cudaFuncSetAttribute(proj_kernel, cudaFuncAttributeMaxDynamicSharedMemorySize, SMEM_SZ);
    cudaFuncSetAttribute(bond_kernel, cudaFuncAttributeMaxDynamicSharedMemorySize, SMEM_SZ);
    cudaFuncSetAttribute(tgt_kernel,  cudaFuncAttributeMaxDynamicSharedMemorySize, SMEM_SZ);

    setup_kernel<<<20, NTHR>>>(W_s2e, W_t2e, W_e2e, W_e2t, W_t2t);
    proj_kernel<<<2 * NPB, NTHR, SMEM_SZ>>>(src, tgt);
    bond_kernel<<<(Bz * Ez) / TM, NTHR, SMEM_SZ>>>(bond, so, to, ln1g, ln1b, out0);
    cudaMemcpyAsync(out1, src, (size_t)Bz * NSz * Dd * sizeof(float),
                    cudaMemcpyDeviceToDevice, 0);
    tgt_kernel<<<NPB, NTHR, SMEM_SZ>>>(tgt, coef, eo, ln2g, ln2b, out2);
}

// round 7
// speedup vs baseline: 1.0988x; 1.0988x over previous
#include <cuda_runtime.h>
#include <cuda_bf16.h>
#include <cstdint>

// ---------------- problem constants ----------------
#define Bz  4
#define NSz 10000
#define NTz 10000
#define Ez  160000
#define Kz  16
#define Dd  128
#define TM  128          // rows per CTA tile
#define NTHR 256
#define NPB 313          // ceil(40000/128)
#define DPITCH 132       // D staging pitch (floats); 528B/row, float4-aligned

// ---------------- scratch (__device__ globals; no allocation) ----------------
__device__ float g_sproj[(size_t)Bz * NSz * Dd];
__device__ float g_tproj[(size_t)Bz * NTz * Dd];
__device__ float g_dbond[(size_t)Bz * Ez  * Dd];
// Pre-swizzled bf16 hi/lo images of the 5 weights, B layout B[n][k] = W[k][n].
__device__ uint4 g_Wimg[5][2][2048];

// ---------------- smem layout (byte offsets) ----------------
// A tile is a K-HALF: 128 rows x 64 k bf16 = 16KB per component.
#define SM_AHI 0
#define SM_ALO 16384
#define SM_BHI 32768          // B full: 128 n x 128 k bf16 = 32KB per component
#define SM_BLO 65536
#define SMEM_SZ 98304         // 96KB -> 2 CTAs/SM
#define SM_D   0              // fp32 D staging overlays A/B (128*132*4 = 67584)

// ---------------- low-level helpers ----------------
static __device__ __forceinline__ uint32_t s2u(const void* p) {
    uint32_t a;
    asm("{ .reg .u64 t; cvta.to.shared.u64 t, %1; cvt.u32.u64 %0, t; }" : "=r"(a) : "l"(p));
    return a;
}
static __device__ __forceinline__ void ldsm_x4(uint32_t& r0, uint32_t& r1, uint32_t& r2,
                                               uint32_t& r3, uint32_t addr) {
    asm volatile("ldmatrix.sync.aligned.m8n8.x4.shared.b16 {%0,%1,%2,%3}, [%4];"
                 : "=r"(r0), "=r"(r1), "=r"(r2), "=r"(r3) : "r"(addr));
}
static __device__ __forceinline__ void mma16816(float* c,
        uint32_t a0, uint32_t a1, uint32_t a2, uint32_t a3, uint32_t b0, uint32_t b1) {
    asm volatile(
        "mma.sync.aligned.m16n8k16.row.col.f32.bf16.bf16.f32 "
        "{%0,%1,%2,%3}, {%4,%5,%6,%7}, {%8,%9}, {%0,%1,%2,%3};"
        : "+f"(c[0]), "+f"(c[1]), "+f"(c[2]), "+f"(c[3])
        : "r"(a0), "r"(a1), "r"(a2), "r"(a3), "r"(b0), "r"(b1));
}
static __device__ __forceinline__ float silu_f(float v) {
    return v * (1.0f / (1.0f + __expf(-v)));
}

// fp32[8] -> bf16 hi/lo packed uint4s (hi = rn(x), lo = rn(x - hi))
static __device__ __forceinline__ void cvt8(const float* f, uint4& h4, uint4& l4) {
    uint32_t h[4], l[4];
#pragma unroll
    for (int i = 0; i < 4; ++i) {
        float a = f[2*i], b = f[2*i+1];
        __nv_bfloat162 hh = __floats2bfloat162_rn(a, b);
        float la = a - __bfloat162float(hh.x);
        float lb = b - __bfloat162float(hh.y);
        __nv_bfloat162 ll = __floats2bfloat162_rn(la, lb);
        h[i] = *reinterpret_cast<uint32_t*>(&hh);
        l[i] = *reinterpret_cast<uint32_t*>(&ll);
    }
    h4 = make_uint4(h[0], h[1], h[2], h[3]);
    l4 = make_uint4(l[0], l[1], l[2], l[3]);
}

// A-half tile: 128B/row (8 x 16B units), XOR swizzle.
static __device__ __forceinline__ uint32_t offA(int row, int u) {
    return (uint32_t)(row * 128 + ((u ^ (row & 7)) << 4));
}
// B tile: 256B/row (16 units), XOR swizzle on low 3 bits of unit.
static __device__ __forceinline__ uint32_t offB(int row, int u) {
    return (uint32_t)(row * 256 + ((u ^ (row & 7)) << 4));
}

// Fill A K-half kh (cols kh*64..+63) for 128 rows. All 256 threads.
static __device__ __forceinline__ void fill_A_half(char* sm, const float* __restrict__ X,
                                                   size_t row0, size_t total, int kh, int tid) {
#pragma unroll
    for (int it = 0; it < 4; ++it) {
        int idx = tid + it * NTHR;        // 0..1023 = 128 rows x 8 units
        int row = idx >> 3;
        int u   = idx & 7;
        size_t g = row0 + row;
        if (g < total) {
            const float4* p = (const float4*)(X + g * Dd + kh * 64 + u * 8);
            float4 v0 = p[0], v1 = p[1];
            float f[8] = {v0.x, v0.y, v0.z, v0.w, v1.x, v1.y, v1.z, v1.w};
            uint4 h, l; cvt8(f, h, l);
            uint32_t off = offA(row, u);
            *(uint4*)(sm + SM_AHI + off) = h;
            *(uint4*)(sm + SM_ALO + off) = l;
        }
    }
}

// Copy pre-swizzled full weight image into B buffers. All 256 threads.
static __device__ __forceinline__ void copy_B(char* sm, int wi, int tid) {
    const uint4* hi = g_Wimg[wi][0];
    const uint4* lo = g_Wimg[wi][1];
    uint4* dh = (uint4*)(sm + SM_BHI);
    uint4* dl = (uint4*)(sm + SM_BLO);
#pragma unroll
    for (int it = 0; it < 8; ++it) {
        int i = tid + it * NTHR;
        dh[i] = hi[i];
        dl[i] = lo[i];
    }
}

// One GEMM term over a K-half: acc += A_half(a_off) @ B(b_off, half kh)^T.
static __device__ __forceinline__ void warp_gemm_term(
        uint32_t sb, uint32_t a_off, uint32_t b_off, int kh,
        int mq, int nh, int lane, float acc[2][8][4]) {
    int x  = lane & 7;
    int rA = (lane & 7) + ((lane >> 3) & 1) * 8;
    int uA = lane >> 4;
    int rB = (lane & 7) + ((lane >> 4) << 3);
    int uB = (lane >> 3) & 1;
    uint32_t baseA0 = sb + a_off + (uint32_t)((mq * 32 + rA) * 128);
    uint32_t baseA1 = baseA0 + 16 * 128;
    uint32_t baseB[4];
#pragma unroll
    for (int nb = 0; nb < 4; ++nb)
        baseB[nb] = sb + b_off + (uint32_t)((nh * 64 + nb * 16 + rB) * 256);
#pragma unroll
    for (int ks = 0; ks < 4; ++ks) {
        uint32_t oA = (uint32_t)(((ks * 2 + uA) ^ x) << 4);
        uint32_t oB = (uint32_t)(((kh * 8 + ks * 2 + uB) ^ x) << 4);
        uint32_t a0, a1, a2, a3, a4, a5, a6, a7;
        ldsm_x4(a0, a1, a2, a3, baseA0 + oA);
        ldsm_x4(a4, a5, a6, a7, baseA1 + oA);
#pragma unroll
        for (int nb = 0; nb < 4; ++nb) {
            uint32_t b0, b1, b2, b3;
            ldsm_x4(b0, b1, b2, b3, baseB[nb] + oB);
            mma16816(acc[0][2*nb],     a0, a1, a2, a3, b0, b1);
            mma16816(acc[0][2*nb + 1], a0, a1, a2, a3, b2, b3);
            mma16816(acc[1][2*nb],     a4, a5, a6, a7, b0, b1);
            mma16816(acc[1][2*nb + 1], a4, a5, a6, a7, b2, b3);
        }
    }
}

static __device__ __forceinline__ void gemm3_half(uint32_t sb, int kh, int mq, int nh,
                                                  int lane, float acc[2][8][4]) {
    warp_gemm_term(sb, SM_AHI, SM_BHI, kh, mq, nh, lane, acc);   // hi*hi
    warp_gemm_term(sb, SM_AHI, SM_BLO, kh, mq, nh, lane, acc);   // hi*lo
    warp_gemm_term(sb, SM_ALO, SM_BHI, kh, mq, nh, lane, acc);   // lo*hi
}

// Stage accumulators into smem D (fp32, pitch DPITCH). Caller syncs before/after.
static __device__ __forceinline__ void store_D(char* sm, int mq, int nh, int lane,
                                               float acc[2][8][4]) {
    float* D = (float*)(sm + SM_D);
#pragma unroll
    for (int i = 0; i < 2; ++i) {
        int r0 = mq * 32 + i * 16 + (lane >> 2);
#pragma unroll
        for (int j = 0; j < 8; ++j) {
            int c = nh * 64 + j * 8 + (lane & 3) * 2;
            *(float2*)(D + r0 * DPITCH + c)       = make_float2(acc[i][j][0], acc[i][j][1]);
            *(float2*)(D + (r0 + 8) * DPITCH + c) = make_float2(acc[i][j][2], acc[i][j][3]);
        }
    }
}

// ---------------- kernel 0: split all 5 weights into swizzled bf16 images ----------------
extern "C" __global__ void __launch_bounds__(NTHR, 4)
setup_kernel(const float* __restrict__ W0, const float* __restrict__ W1,
             const float* __restrict__ W2, const float* __restrict__ W3,
             const float* __restrict__ W4) {
    const float* Ws[5] = {W0, W1, W2, W3, W4};
    int w = blockIdx.x >> 2, part = blockIdx.x & 3;
    const float* W = Ws[w];
    int tid = threadIdx.x;
#pragma unroll
    for (int it = 0; it < 2; ++it) {
        int idx = part * 512 + tid + it * NTHR;   // 0..2047 = 128 n-rows x 16 units
        int n = idx >> 4;
        int u = idx & 15;
        float f[8];
#pragma unroll
        for (int i = 0; i < 8; ++i) f[i] = W[(u * 8 + i) * Dd + n];   // B[n][k]=W[k][n]
        uint4 h, l; cvt8(f, h, l);
        uint32_t off16 = offB(n, u) >> 4;
        g_Wimg[w][0][off16] = h;
        g_Wimg[w][1][off16] = l;
    }
}

// ---------------- kernel 1: node projections ----------------
extern "C" __global__ void __launch_bounds__(NTHR, 2)
proj_kernel(const float* __restrict__ src, const float* __restrict__ tgt) {
    extern __shared__ char sm[];
    uint32_t sb = s2u(sm);
    int tid = threadIdx.x;
    int lane = tid & 31, w = tid >> 5, mq = w & 3, nh = w >> 2;
    const size_t total = (size_t)Bz * NSz;   // 40000

    int blk = blockIdx.x;
    const float* X; int wi; float* Y;
    if (blk < NPB) { X = src; wi = 0; Y = g_sproj; }
    else           { blk -= NPB; X = tgt; wi = 1; Y = g_tproj; }
    size_t row0 = (size_t)blk * TM;

    copy_B(sm, wi, tid);
    fill_A_half(sm, X, row0, total, 0, tid);
    __syncthreads();

    float acc[2][8][4] = {};
    gemm3_half(sb, 0, mq, nh, lane, acc);
    __syncthreads();
    fill_A_half(sm, X, row0, total, 1, tid);
    __syncthreads();
    gemm3_half(sb, 1, mq, nh, lane, acc);
    __syncthreads();
    store_D(sm, mq, nh, lane, acc);
    __syncthreads();

    const float* D = (const float*)(sm + SM_D);
#pragma unroll
    for (int it = 0; it < 16; ++it) {
        int unit = tid + it * NTHR;       // 128 rows x 32 float4
        int row = unit >> 5;
        int c4  = (unit & 31) * 4;
        size_t g = row0 + row;
        if (g < total)
            *(float4*)(Y + g * Dd + c4) = *(const float4*)(D + row * DPITCH + c4);
    }
}

// ---------------- kernel 2: bond update ----------------
extern "C" __global__ void __launch_bounds__(NTHR, 2)
bond_kernel(const float* __restrict__ bond,
            const int* __restrict__ src_order, const int* __restrict__ tgt_order,
            const float* __restrict__ lg, const float* __restrict__ lb,
            float* __restrict__ out0) {
    extern __shared__ char sm[];
    uint32_t sb = s2u(sm);
    int tid = threadIdx.x;
    int lane = tid & 31, w = tid >> 5, mq = w & 3, nh = w >> 2;
    size_t row0 = (size_t)blockIdx.x * TM;

    copy_B(sm, 2, tid);                      // W_e2e
    fill_A_half(sm, bond, row0, (size_t)Bz * Ez, 0, tid);
    __syncthreads();

    float acc[2][8][4] = {};
    gemm3_half(sb, 0, mq, nh, lane, acc);
    __syncthreads();
    fill_A_half(sm, bond, row0, (size_t)Bz * Ez, 1, tid);
    __syncthreads();
    gemm3_half(sb, 1, mq, nh, lane, acc);
    __syncthreads();
    store_D(sm, mq, nh, lane, acc);
    __syncthreads();

    // Epilogue: 4 threads per row x 32 cols, 2 rows per thread.
    const float* D = (const float*)(sm + SM_D);
    int q = tid & 3, rb = tid >> 2;
#pragma unroll
    for (int hp = 0; hp < 2; ++hp) {
        int r = rb + hp * 64;
        int c0 = q * 32;
        size_t grow = row0 + r;
        int b = (int)(grow / Ez);
        int e = (int)(grow - (size_t)b * Ez);
        int so = src_order[e];
        int to = tgt_order[e];
        const float4* sp = (const float4*)(g_sproj + ((size_t)b * NSz + so) * Dd + c0);
        const float4* tp = (const float4*)(g_tproj + ((size_t)b * NTz + to) * Dd + c0);
        const float*  dr = D + r * DPITCH + c0;

        float v[32];
        float s = 0.f, s2 = 0.f;
#pragma unroll
        for (int j = 0; j < 8; ++j) {
            float4 a = sp[j], c = tp[j];
            float v0 = silu_f(dr[4*j]     + a.x + c.x);
            float v1 = silu_f(dr[4*j + 1] + a.y + c.y);
            float v2 = silu_f(dr[4*j + 2] + a.z + c.z);
            float v3 = silu_f(dr[4*j + 3] + a.w + c.w);
            v[4*j] = v0; v[4*j+1] = v1; v[4*j+2] = v2; v[4*j+3] = v3;
            s  += v0 + v1 + v2 + v3;
            s2 += v0*v0 + v1*v1 + v2*v2 + v3*v3;
        }
        s  += __shfl_xor_sync(0xffffffffu, s, 1);
        s2 += __shfl_xor_sync(0xffffffffu, s2, 1);
        s  += __shfl_xor_sync(0xffffffffu, s, 2);
        s2 += __shfl_xor_sync(0xffffffffu, s2, 2);
        float m   = s * (1.0f / Dd);
        float var = s2 * (1.0f / Dd) - m * m;
        float rs  = rsqrtf(var + 1e-5f);

        const float4* gg = (const float4*)(lg + c0);
        const float4* bb = (const float4*)(lb + c0);
        const float4* bo = (const float4*)(bond + grow * Dd + c0);
        float4* dbw = (float4*)(g_dbond + grow * Dd + c0);
        float4* ow  = (float4*)(out0    + grow * Dd + c0);
#pragma unroll
        for (int j = 0; j < 8; ++j) {
            float4 g4 = gg[j], b4 = bb[j], bd = bo[j];
            float y0 = (v[4*j]   - m) * rs * g4.x + b4.x;
            float y1 = (v[4*j+1] - m) * rs * g4.y + b4.y;
            float y2 = (v[4*j+2] - m) * rs * g4.z + b4.z;
            float y3 = (v[4*j+3] - m) * rs * g4.w + b4.w;
            dbw[j] = make_float4(y0, y1, y2, y3);
            ow[j]  = make_float4(bd.x + y0, bd.y + y1, bd.z + y2, bd.w + y3);
        }
    }
}

// Fill A K-half from bond_reduce gather (tgt kernel round 1). 2 threads/row.
static __device__ __forceinline__ void fill_R_half(char* sm,
        const float* __restrict__ coef, const int* __restrict__ eorder,
        size_t row0, size_t total, int kh, int tid) {
    int hc = tid & 1;                 // 32-col sub-half within the K-half
    int r  = tid >> 1;                // 0..127
    size_t grow = row0 + r;
    if (grow >= total) return;
    int b  = (int)(grow / NTz);
    int tt = (int)(grow - (size_t)b * NTz);
    const int*   eo = eorder + tt * Kz;
    const float* cf = coef   + tt * Kz;
    float4 a4[8];
#pragma unroll
    for (int j = 0; j < 8; ++j) a4[j] = make_float4(0.f, 0.f, 0.f, 0.f);
    for (int k = 0; k < Kz; ++k) {
        float c = cf[k];
        const float4* p = (const float4*)(g_dbond + ((size_t)b * Ez + eo[k]) * Dd
                                          + kh * 64 + hc * 32);
#pragma unroll
        for (int j = 0; j < 8; ++j) {
            float4 vv = p[j];
            a4[j].x = fmaf(c, vv.x, a4[j].x);
            a4[j].y = fmaf(c, vv.y, a4[j].y);
            a4[j].z = fmaf(c, vv.z, a4[j].z);
            a4[j].w = fmaf(c, vv.w, a4[j].w);
        }
    }
#pragma unroll
    for (int uu = 0; uu < 4; ++uu) {
        float f[8] = {a4[2*uu].x   * (1.0f/Kz), a4[2*uu].y   * (1.0f/Kz),
                      a4[2*uu].z   * (1.0f/Kz), a4[2*uu].w   * (1.0f/Kz),
                      a4[2*uu+1].x * (1.0f/Kz), a4[2*uu+1].y * (1.0f/Kz),
                      a4[2*uu+1].z * (1.0f/Kz), a4[2*uu+1].w * (1.0f/Kz)};
        uint4 h, l; cvt8(f, h, l);
        uint32_t off = offA(r, hc * 4 + uu);
        *(uint4*)(sm + SM_AHI + off) = h;
        *(uint4*)(sm + SM_ALO + off) = l;
    }
}

// ---------------- kernel 3: target update ----------------
extern "C" __global__ void __launch_bounds__(NTHR, 2)
tgt_kernel(const float* __restrict__ tgt,
           const float* __restrict__ coef, const int* __restrict__ eorder,
           const float* __restrict__ lg, const float* __restrict__ lb,
           float* __restrict__ out2) {
    extern __shared__ char sm[];
    uint32_t sb = s2u(sm);
    int tid = threadIdx.x;
    int lane = tid & 31, w = tid >> 5, mq = w & 3, nh = w >> 2;
    const size_t total = (size_t)Bz * NTz;   // 40000
    size_t row0 = (size_t)blockIdx.x * TM;

    // Round 1: bond_reduce @ W_e2t
    copy_B(sm, 3, tid);
    fill_R_half(sm, coef, eorder, row0, total, 0, tid);
    __syncthreads();

    float acc[2][8][4] = {};
    gemm3_half(sb, 0, mq, nh, lane, acc);
    __syncthreads();
    fill_R_half(sm, coef, eorder, row0, total, 1, tid);
    __syncthreads();
    gemm3_half(sb, 1, mq, nh, lane, acc);
    __syncthreads();

    // Round 2: += tgt @ W_t2t
    copy_B(sm, 4, tid);
    fill_A_half(sm, tgt, row0, total, 0, tid);
    __syncthreads();
    gemm3_half(sb, 0, mq, nh, lane, acc);
    __syncthreads();
    fill_A_half(sm, tgt, row0, total, 1, tid);
    __syncthreads();
    gemm3_half(sb, 1, mq, nh, lane, acc);
    __syncthreads();
    store_D(sm, mq, nh, lane, acc);
    __syncthreads();

    const float* D = (const float*)(sm + SM_D);
    int q = tid & 3, rb = tid >> 2;
#pragma unroll
    for (int hp = 0; hp < 2; ++hp) {
        int r = rb + hp * 64;
        int c0 = q * 32;
        size_t grow = row0 + r;
        const float* dr = D + r * DPITCH + c0;

        float v[32];
        float s = 0.f, s2 = 0.f;
#pragma unroll
        for (int j = 0; j < 8; ++j) {
            float v0 = silu_f(dr[4*j]);
            float v1 = silu_f(dr[4*j + 1]);
            float v2 = silu_f(dr[4*j + 2]);
            float v3 = silu_f(dr[4*j + 3]);
            v[4*j] = v0; v[4*j+1] = v1; v[4*j+2] = v2; v[4*j+3] = v3;
            s  += v0 + v1 + v2 + v3;
            s2 += v0*v0 + v1*v1 + v2*v2 + v3*v3;
        }
        s  += __shfl_xor_sync(0xffffffffu, s, 1);
        s2 += __shfl_xor_sync(0xffffffffu, s2, 1);
        s  += __shfl_xor_sync(0xffffffffu, s, 2);
        s2 += __shfl_xor_sync(0xffffffffu, s2, 2);
        float m   = s * (1.0f / Dd);
        float var = s2 * (1.0f / Dd) - m * m;
        float rs  = rsqrtf(var + 1e-5f);

        if (grow < total) {
            const float4* gg = (const float4*)(lg + c0);
            const float4* bb = (const float4*)(lb + c0);
            const float4* tv = (const float4*)(tgt + grow * Dd + c0);
            float4* ow = (float4*)(out2 + grow * Dd + c0);
#pragma unroll
            for (int j = 0; j < 8; ++j) {
                float4 g4 = gg[j], b4 = bb[j], t4 = tv[j];
                ow[j] = make_float4(t4.x + (v[4*j]   - m) * rs * g4.x + b4.x,
                                    t4.y + (v[4*j+1] - m) * rs * g4.y + b4.y,
                                    t4.z + (v[4*j+2] - m) * rs * g4.z + b4.z,
                                    t4.w + (v[4*j+3] - m) * rs * g4.w + b4.w);
            }
        }
    }
}

// ---------------- launcher ----------------
extern "C" void kernel_launch(void* const* d_in, const int* in_sizes, int n_in,
                              void* d_out, int out_size) {
    const float* bond  = (const float*)d_in[0];
    const float* src   = (const float*)d_in[1];
    const float* tgt   = (const float*)d_in[2];
    const float* W_s2e = (const float*)d_in[3];
    const float* W_t2e = (const float*)d_in[4];
    const float* W_e2e = (const float*)d_in[5];
    const float* ln1g  = (const float*)d_in[6];
    const float* ln1b  = (const float*)d_in[7];
    const float* W_e2t = (const float*)d_in[8];
    const float* W_t2t = (const float*)d_in[9];
    const float* ln2g  = (const float*)d_in[10];
    const float* ln2b  = (const float*)d_in[11];
    const float* coef  = (const float*)d_in[12];
    const int*   so    = (const int*)d_in[13];
    const int*   to    = (const int*)d_in[14];
    const int*   eo    = (const int*)d_in[15];

    float* out0 = (float*)d_out;                         // [B,E,D]
    float* out1 = out0 + (size_t)Bz * Ez  * Dd;          // [B,NS,D] passthrough
    float* out2 = out1 + (size_t)Bz * NSz * Dd;          // [B,NT,D]

    cudaFuncSetAttribute(proj_kernel, cudaFuncAttributeMaxDynamicSharedMemorySize, SMEM_SZ);
    cudaFuncSetAttribute(bond_kernel, cudaFuncAttributeMaxDynamicSharedMemorySize, SMEM_SZ);
    cudaFuncSetAttribute(tgt_kernel,  cudaFuncAttributeMaxDynamicSharedMemorySize, SMEM_SZ);

    setup_kernel<<<20, NTHR>>>(W_s2e, W_t2e, W_e2e, W_e2t, W_t2t);
    proj_kernel<<<2 * NPB, NTHR, SMEM_SZ>>>(src, tgt);
    bond_kernel<<<(Bz * Ez) / TM, NTHR, SMEM_SZ>>>(bond, so, to, ln1g, ln1b, out0);
    cudaMemcpyAsync(out1, src, (size_t)Bz * NSz * Dd * sizeof(float),
                    cudaMemcpyDeviceToDevice, 0);
    tgt_kernel<<<NPB, NTHR, SMEM_SZ>>>(tgt, coef, eo, ln2g, ln2b, out2);
}

// round 8
// speedup vs baseline: 1.4338x; 1.3049x over previous
#include <cuda_runtime.h>
#include <cstdint>

// Problem constants
#define Bz  4
#define NSz 10000
#define NTz 10000
#define Ez  160000
#define Kz  16
#define Dd  128
#define BM  64          // rows per block tile
#define NTHR 256
#define AP  66          // padded pitch for transposed A tile (even -> 8B aligned row-pairs)

// Scratch (allocation-free rule: __device__ globals)
__device__ float g_sproj[(size_t)Bz * NSz * Dd];   // src @ W_s2e
__device__ float g_tproj[(size_t)Bz * NTz * Dd];   // tgt @ W_t2e
__device__ float g_dbond[(size_t)Bz * Ez  * Dd];   // post-LN d_bond

// ---------------- f32x2 packed helpers ----------------
static __device__ __forceinline__ uint64_t pk2(float x, float y) {
    uint64_t r; asm("mov.b64 %0, {%1, %2};" : "=l"(r) : "f"(x), "f"(y)); return r;
}
static __device__ __forceinline__ void fma2(uint64_t& d, uint64_t a, uint64_t b) {
    asm("fma.rn.f32x2 %0, %1, %2, %0;" : "+l"(d) : "l"(a), "l"(b));
}
static __device__ __forceinline__ float2 upk(uint64_t v) {
    float2 f; asm("mov.b64 {%0, %1}, %2;" : "=f"(f.x), "=f"(f.y) : "l"(v)); return f;
}

// ---------------- shared helpers ----------------
__device__ __forceinline__ void load_W(float* Ws, const float* __restrict__ W, int tid) {
    float4* dst = (float4*)Ws;
    const float4* src = (const float4*)W;
    #pragma unroll
    for (int i = 0; i < (Dd * Dd / 4) / NTHR; ++i)   // 16 iters
        dst[tid + i * NTHR] = src[tid + i * NTHR];
}

// Load BM x 128 tile of A, transposed into As[k][row] with pitch AP.
__device__ __forceinline__ void load_A_T(float* As, const float* __restrict__ A,
                                         size_t row0, int tid) {
    #pragma unroll
    for (int i = 0; i < (BM * Dd) / NTHR; ++i) {     // 16 iters
        int idx = tid + i * NTHR;
        int r = idx >> 7;
        int k = idx & 127;
        As[k * AP + r] = A[(row0 + r) * Dd + k];
    }
}

// 64x128x128 fp32 GEMM accumulate using packed f32x2.
// Warp w owns local rows [8w, 8w+8) as 4 row-pairs; lane c owns cols [4c, 4c+4).
// acc[p][c] = {D(2p, c), D(2p+1, c)} packed.
__device__ __forceinline__ void gemm128(const float* Ws, const float* As,
                                        uint64_t acc[4][4], int wrow0, int c4) {
    #pragma unroll 4
    for (int k = 0; k < Dd; ++k) {
        const float4 b4 = *(const float4*)(Ws + k * Dd + c4);
        uint64_t bx = pk2(b4.x, b4.x), by = pk2(b4.y, b4.y);
        uint64_t bz = pk2(b4.z, b4.z), bw = pk2(b4.w, b4.w);
        const uint64_t* ap = (const uint64_t*)(As + k * AP + wrow0);
        #pragma unroll
        for (int p = 0; p < 4; ++p) {
            uint64_t a2 = ap[p];
            fma2(acc[p][0], a2, bx);
            fma2(acc[p][1], a2, by);
            fma2(acc[p][2], a2, bz);
            fma2(acc[p][3], a2, bw);
        }
    }
}

// Unpack packed accumulators into af[8][4] (row-major within the 8-row strip).
__device__ __forceinline__ void unpack_acc(const uint64_t acc[4][4], float af[8][4]) {
    #pragma unroll
    for (int p = 0; p < 4; ++p)
        #pragma unroll
        for (int c = 0; c < 4; ++c) {
            float2 v = upk(acc[p][c]);
            af[2*p][c]     = v.x;
            af[2*p + 1][c] = v.y;
        }
}

__device__ __forceinline__ float warp_sum(float v) {
    #pragma unroll
    for (int o = 16; o; o >>= 1) v += __shfl_xor_sync(0xffffffffu, v, o);
    return v;
}

__device__ __forceinline__ float silu(float v) {
    return v * (1.0f / (1.0f + __expf(-v)));
}

// ---------------- kernel 1: both node projections ----------------
extern "C" __global__ void __launch_bounds__(NTHR, 2)
proj_kernel(const float* __restrict__ src, const float* __restrict__ tgt,
            const float* __restrict__ W_s2e, const float* __restrict__ W_t2e) {
    extern __shared__ float sm[];
    float* Ws = sm;
    float* As = sm + Dd * Dd;
    int tid = threadIdx.x;

    int blk = blockIdx.x;
    const int NBLK_S = (Bz * NSz) / BM;   // 625
    const float* X; const float* W; float* Y;
    if (blk < NBLK_S) { X = src; W = W_s2e; Y = g_sproj; }
    else              { blk -= NBLK_S; X = tgt; W = W_t2e; Y = g_tproj; }

    size_t row0 = (size_t)blk * BM;
    load_W(Ws, W, tid);
    load_A_T(As, X, row0, tid);
    __syncthreads();

    uint64_t acc[4][4] = {};
    int c4 = (tid & 31) * 4, wrow0 = (tid >> 5) * 8;
    gemm128(Ws, As, acc, wrow0, c4);

    float af[8][4];
    unpack_acc(acc, af);
    #pragma unroll
    for (int i = 0; i < 8; ++i) {
        size_t row = row0 + wrow0 + i;
        *(float4*)(Y + row * Dd + c4) =
            make_float4(af[i][0], af[i][1], af[i][2], af[i][3]);
    }
}

// ---------------- kernel 2: bond update (the big one) ----------------
extern "C" __global__ void __launch_bounds__(NTHR, 2)
bond_kernel(const float* __restrict__ bond, const float* __restrict__ W_e2e,
            const int* __restrict__ src_order, const int* __restrict__ tgt_order,
            const float* __restrict__ lg, const float* __restrict__ lb,
            float* __restrict__ out0) {
    extern __shared__ float sm[];
    float* Ws = sm;
    float* As = sm + Dd * Dd;
    int tid = threadIdx.x;
    size_t row0 = (size_t)blockIdx.x * BM;

    load_W(Ws, W_e2e, tid);
    load_A_T(As, bond, row0, tid);
    __syncthreads();

    uint64_t acc[4][4] = {};
    int c4 = (tid & 31) * 4, wrow0 = (tid >> 5) * 8;
    gemm128(Ws, As, acc, wrow0, c4);

    float af[8][4];
    unpack_acc(acc, af);

    float4 g4  = *(const float4*)(lg + c4);
    float4 bb4 = *(const float4*)(lb + c4);

    #pragma unroll
    for (int i = 0; i < 8; ++i) {
        size_t grow = row0 + wrow0 + i;            // flattened (b, e)
        int b = (int)(grow / Ez);
        int e = (int)(grow - (size_t)b * Ez);
        int so = src_order[e];
        int to = tgt_order[e];
        float4 sp = *(const float4*)(g_sproj + ((size_t)b * NSz + so) * Dd + c4);
        float4 tp = *(const float4*)(g_tproj + ((size_t)b * NTz + to) * Dd + c4);

        float u0 = silu(af[i][0] + sp.x + tp.x);
        float u1 = silu(af[i][1] + sp.y + tp.y);
        float u2 = silu(af[i][2] + sp.z + tp.z);
        float u3 = silu(af[i][3] + sp.w + tp.w);

        float s  = warp_sum(u0 + u1 + u2 + u3);
        float s2 = warp_sum(u0*u0 + u1*u1 + u2*u2 + u3*u3);
        float m   = s  * (1.0f / Dd);
        float var = s2 * (1.0f / Dd) - m * m;
        float rs  = rsqrtf(var + 1e-5f);

        float y0 = (u0 - m) * rs * g4.x + bb4.x;
        float y1 = (u1 - m) * rs * g4.y + bb4.y;
        float y2 = (u2 - m) * rs * g4.z + bb4.z;
        float y3 = (u3 - m) * rs * g4.w + bb4.w;

        *(float4*)(g_dbond + grow * Dd + c4) = make_float4(y0, y1, y2, y3);
        float4 bd = *(const float4*)(bond + grow * Dd + c4);
        *(float4*)(out0 + grow * Dd + c4) =
            make_float4(bd.x + y0, bd.y + y1, bd.z + y2, bd.w + y3);
    }
}

// ---------------- kernel 3: target update ----------------
extern "C" __global__ void __launch_bounds__(NTHR, 2)
tgt_kernel(const float* __restrict__ tgt,
           const float* __restrict__ W_e2t, const float* __restrict__ W_t2t,
           const float* __restrict__ coef, const int* __restrict__ eorder,
           const float* __restrict__ lg, const float* __restrict__ lb,
           float* __restrict__ out2) {
    extern __shared__ float sm[];
    float* Ws = sm;
    float* As = sm + Dd * Dd;
    int tid = threadIdx.x;
    size_t row0 = (size_t)blockIdx.x * BM;

    // Phase A: bond_reduce tile (transposed) + W_e2t
    load_W(Ws, W_e2t, tid);
    #pragma unroll 2
    for (int it = 0; it < (BM * Dd) / NTHR; ++it) {  // 16 iters
        int idx = tid + it * NTHR;
        int r = idx >> 7;
        int j = idx & 127;
        size_t grow = row0 + r;
        int b = (int)(grow / NTz);
        int t = (int)(grow - (size_t)b * NTz);
        const int*   eo = eorder + t * Kz;
        const float* cf = coef   + t * Kz;
        float a = 0.0f;
        #pragma unroll
        for (int k = 0; k < Kz; ++k)
            a = fmaf(cf[k], g_dbond[((size_t)b * Ez + eo[k]) * Dd + j], a);
        As[j * AP + r] = a * (1.0f / Kz);
    }
    __syncthreads();

    uint64_t acc[4][4] = {};
    int c4 = (tid & 31) * 4, wrow0 = (tid >> 5) * 8;
    gemm128(Ws, As, acc, wrow0, c4);
    __syncthreads();

    // Phase B: tgt tile + W_t2t, accumulate
    load_W(Ws, W_t2t, tid);
    load_A_T(As, tgt, row0, tid);
    __syncthreads();
    gemm128(Ws, As, acc, wrow0, c4);

    float af[8][4];
    unpack_acc(acc, af);

    float4 g4  = *(const float4*)(lg + c4);
    float4 bb4 = *(const float4*)(lb + c4);

    #pragma unroll
    for (int i = 0; i < 8; ++i) {
        size_t grow = row0 + wrow0 + i;
        float u0 = silu(af[i][0]);
        float u1 = silu(af[i][1]);
        float u2 = silu(af[i][2]);
        float u3 = silu(af[i][3]);

        float s  = warp_sum(u0 + u1 + u2 + u3);
        float s2 = warp_sum(u0*u0 + u1*u1 + u2*u2 + u3*u3);
        float m   = s  * (1.0f / Dd);
        float var = s2 * (1.0f / Dd) - m * m;
        float rs  = rsqrtf(var + 1e-5f);

        float y0 = (u0 - m) * rs * g4.x + bb4.x;
        float y1 = (u1 - m) * rs * g4.y + bb4.y;
        float y2 = (u2 - m) * rs * g4.z + bb4.z;
        float y3 = (u3 - m) * rs * g4.w + bb4.w;

        float4 tv = *(const float4*)(tgt + grow * Dd + c4);
        *(float4*)(out2 + grow * Dd + c4) =
            make_float4(tv.x + y0, tv.y + y1, tv.z + y2, tv.w + y3);
    }
}

// ---------------- launcher ----------------
extern "C" void kernel_launch(void* const* d_in, const int* in_sizes, int n_in,
                              void* d_out, int out_size) {
    const float* bond  = (const float*)d_in[0];
    const float* src   = (const float*)d_in[1];
    const float* tgt   = (const float*)d_in[2];
    const float* W_s2e = (const float*)d_in[3];
    const float* W_t2e = (const float*)d_in[4];
    const float* W_e2e = (const float*)d_in[5];
    const float* ln1g  = (const float*)d_in[6];
    const float* ln1b  = (const float*)d_in[7];
    const float* W_e2t = (const float*)d_in[8];
    const float* W_t2t = (const float*)d_in[9];
    const float* ln2g  = (const float*)d_in[10];
    const float* ln2b  = (const float*)d_in[11];
    const float* coef  = (const float*)d_in[12];
    const int*   so    = (const int*)d_in[13];
    const int*   to    = (const int*)d_in[14];
    const int*   eo    = (const int*)d_in[15];

    float* out0 = (float*)d_out;                         // bond + d_bond  [B,E,D]
    float* out1 = out0 + (size_t)Bz * Ez  * Dd;          // src passthrough [B,NS,D]
    float* out2 = out1 + (size_t)Bz * NSz * Dd;          // tgt + d_tgt    [B,NT,D]

    const int smem = (Dd * Dd + Dd * AP) * (int)sizeof(float);   // 99328 B
    cudaFuncSetAttribute(proj_kernel, cudaFuncAttributeMaxDynamicSharedMemorySize, smem);
    cudaFuncSetAttribute(bond_kernel, cudaFuncAttributeMaxDynamicSharedMemorySize, smem);
    cudaFuncSetAttribute(tgt_kernel,  cudaFuncAttributeMaxDynamicSharedMemorySize, smem);

    proj_kernel<<<(Bz * NSz + Bz * NTz) / BM, NTHR, smem>>>(src, tgt, W_s2e, W_t2e);
    bond_kernel<<<(Bz * Ez) / BM, NTHR, smem>>>(bond, W_e2e, so, to, ln1g, ln1b, out0);
    cudaMemcpyAsync(out1, src, (size_t)Bz * NSz * Dd * sizeof(float),
                    cudaMemcpyDeviceToDevice, 0);
    tgt_kernel<<<(Bz * NTz) / BM, NTHR, smem>>>(tgt, W_e2t, W_t2t, coef, eo,
                                                ln2g, ln2b, out2);
}